// round 10
// baseline (speedup 1.0000x reference)
// R9: (1) GEMM converted to cp.async.cg 3-stage k16 pipeline (one bar/iter, 2 blk/SM);
//     (2) recurrence waits per-warp on its 8 producer blocks only (no global bar).
#include <cuda_runtime.h>
#include <cuda_bf16.h>
#include <math.h>
#include <stdint.h>

#define Bz 32
#define SL 512
#define VD 768
#define HD 512
#define NT 5120     // fused N: 2048 (Wx_f) + 2048 (Wx_b) + 1024 (Ws)
#define NBLK 128    // 64 fwd + 64 bwd persistent blocks

// ---------------- scratch (device globals; no allocation allowed) ----------------
__device__ __align__(16) float g_xgf[(size_t)SL * 2048 * Bz];   // [t][g][b]
__device__ __align__(16) float g_xgb[(size_t)SL * 2048 * Bz];   // [t][g][b]
__device__ __align__(16) float g_skip[(size_t)SL * 1024 * Bz];  // [t][g][b]
__device__ __align__(16) float g_hsf[(size_t)SL * HD * Bz];     // [t][j][b]
__device__ __align__(16) float g_hsb[(size_t)SL * HD * Bz];     // [t][j][b]
// h broadcast in A-fragment layout, bf16 hi/lo planes: [dir][parity][8192 u32]
__device__ __align__(16) uint32_t g_hbh[2 * 2 * 8192];
__device__ __align__(16) uint32_t g_hbl[2 * 2 * 8192];
__device__ int g_flag[NBLK];

// bf16-split GEMM operands
__device__ __align__(16) __nv_bfloat16 g_Ah[(size_t)(Bz * SL) * VD];  // [m][k]
__device__ __align__(16) __nv_bfloat16 g_Al[(size_t)(Bz * SL) * VD];
__device__ __align__(16) __nv_bfloat16 g_Wth[(size_t)NT * VD];        // W^T [n][k]
__device__ __align__(16) __nv_bfloat16 g_Wtl[(size_t)NT * VD];
__device__ __align__(16) float g_biasc[NT];

// ---------------- helpers ----------------
__device__ __forceinline__ void bsplit(float x, __nv_bfloat16& hi, __nv_bfloat16& lo) {
    hi = __float2bfloat16_rn(x);
    lo = __float2bfloat16_rn(x - __bfloat162float(hi));
}
__device__ __forceinline__ uint32_t bpack(__nv_bfloat16 a, __nv_bfloat16 b) {
    uint16_t ua = *(uint16_t*)&a, ub = *(uint16_t*)&b;
    return (uint32_t)ua | ((uint32_t)ub << 16);
}
__device__ __forceinline__ void mma16(float* d, const uint32_t* a, const uint32_t* b) {
    asm volatile(
        "mma.sync.aligned.m16n8k16.row.col.f32.bf16.bf16.f32 "
        "{%0,%1,%2,%3}, {%4,%5,%6,%7}, {%8,%9}, {%0,%1,%2,%3};"
        : "+f"(d[0]), "+f"(d[1]), "+f"(d[2]), "+f"(d[3])
        : "r"(a[0]), "r"(a[1]), "r"(a[2]), "r"(a[3]), "r"(b[0]), "r"(b[1]));
}
__device__ __forceinline__ int ld_acq_i(const int* p) {
    int v;
    asm volatile("ld.acquire.gpu.s32 %0, [%1];" : "=r"(v) : "l"(p) : "memory");
    return v;
}
__device__ __forceinline__ void st_rel_i(int* p, int v) {
    asm volatile("st.release.gpu.s32 [%0], %1;" :: "l"(p), "r"(v) : "memory");
}
__device__ __forceinline__ void cp16(uint32_t dst, const void* src) {
    asm volatile("cp.async.cg.shared.global [%0], [%1], 16;" :: "r"(dst), "l"(src));
}
__device__ __forceinline__ uint32_t smem_u32(const void* p) {
    uint32_t a;
    asm("{ .reg .u64 t; cvta.to.shared.u64 t, %1; cvt.u32.u64 %0, t; }" : "=r"(a) : "l"(p));
    return a;
}
__device__ __forceinline__ float sigm_f(float x) { return __fdividef(1.f, 1.f + __expf(-x)); }
__device__ __forceinline__ float tanh_f(float x) { return __fdividef(2.f, 1.f + __expf(-2.f * x)) - 1.f; }

// ---------------- init: flags + bias concat ----------------
__global__ void init_misc(const float* __restrict__ bf, const float* __restrict__ bb_,
                          const float* __restrict__ bs) {
    int c = blockIdx.x * 256 + threadIdx.x;
    if (c < NT)
        g_biasc[c] = (c < 2048) ? bf[c] : (c < 4096) ? bb_[c - 2048] : bs[c - 4096];
    if (blockIdx.x == 0 && threadIdx.x < NBLK) g_flag[threadIdx.x] = 0;
}

// ---------------- split A (values -> bf16 hi/lo planes, [m][k]) ----------------
__global__ void split_A(const float* __restrict__ values) {
    const int m = blockIdx.x;              // m = t*32 + b
    const int b = m & 31, t = m >> 5;
    const float* src = values + ((size_t)b * SL + t) * VD;
    for (int v = threadIdx.x; v < VD; v += 256) {
        __nv_bfloat16 hi, lo;
        bsplit(src[v], hi, lo);
        g_Ah[(size_t)m * VD + v] = hi;
        g_Al[(size_t)m * VD + v] = lo;
    }
}

// ---------------- split + transpose W -> [n][k] bf16 hi/lo ----------------
__global__ void split_W(const float* __restrict__ Wxf, const float* __restrict__ Wxb,
                        const float* __restrict__ Ws) {
    __shared__ float tile[32][33];
    const int k0 = blockIdx.x * 32;
    const int n0 = blockIdx.y * 32;
    const int tid = threadIdx.x;
    const int c = tid & 31;
    for (int r = tid >> 5; r < 32; r += 8) {
        int k = k0 + r, n = n0 + c;
        float x = (n < 2048) ? Wxf[(size_t)k * 2048 + n]
                : (n < 4096) ? Wxb[(size_t)k * 2048 + (n - 2048)]
                             : Ws[(size_t)k * 1024 + (n - 4096)];
        tile[r][c] = x;
    }
    __syncthreads();
    for (int r = tid >> 5; r < 32; r += 8) {
        int n = n0 + r, k = k0 + c;
        __nv_bfloat16 hi, lo;
        bsplit(tile[c][r], hi, lo);
        g_Wth[(size_t)n * VD + k] = hi;
        g_Wtl[(size_t)n * VD + k] = lo;
    }
}

// ---------------- fused bf16 3-chain GEMM, cp.async 3-stage pipeline ----------------
// k-tile 16, 48 iters. Stage = 16KB (Ah|Al|Bh|Bl, 128x16 u16 each). 3 stages = 48KB.
#define KT 16
#define NIT (VD / KT)          // 48
#define STG_U16 8192           // u16 per stage
__global__ __launch_bounds__(256, 2) void gemm_mma()
{
    extern __shared__ uint16_t gsm[];   // 3 * 8192 u16

    const int bn = blockIdx.x, bm = blockIdx.y;
    const int tid = threadIdx.x;
    const int wid = tid >> 5, lane = tid & 31;
    const int wm = wid & 3, wn = wid >> 2;
    const int g = lane >> 2, tg = lane & 3;

    float acc[2][8][4];
#pragma unroll
    for (int mt = 0; mt < 2; mt++)
#pragma unroll
        for (int nt = 0; nt < 8; nt++)
#pragma unroll
            for (int i = 0; i < 4; i++) acc[mt][nt][i] = 0.f;

    // cp.async mapping: thread -> one 16B chunk per plane
    const int prow = tid >> 1;                 // 0..127
    const int pk = (tid & 1) * 8;              // u16 offset in row
    const __nv_bfloat16* srcAh = g_Ah + (size_t)(bm * 128 + prow) * VD + pk;
    const __nv_bfloat16* srcAl = g_Al + (size_t)(bm * 128 + prow) * VD + pk;
    const __nv_bfloat16* srcBh = g_Wth + (size_t)(bn * 128 + prow) * VD + pk;
    const __nv_bfloat16* srcBl = g_Wtl + (size_t)(bn * 128 + prow) * VD + pk;
    const uint32_t dbase = smem_u32(gsm) + (prow * 16 + pk) * 2;   // byte addr

#define ISSUE(st, k0) do {                         \
        uint32_t d = dbase + (st) * 16384;         \
        cp16(d,         srcAh + (k0));             \
        cp16(d + 4096,  srcAl + (k0));             \
        cp16(d + 8192,  srcBh + (k0));             \
        cp16(d + 12288, srcBl + (k0));             \
    } while (0)

    ISSUE(0, 0);
    asm volatile("cp.async.commit_group;" ::: "memory");
    ISSUE(1, KT);
    asm volatile("cp.async.commit_group;" ::: "memory");

    for (int it = 0; it < NIT; it++) {
        asm volatile("cp.async.wait_group 1;" ::: "memory");
        __syncthreads();

        int pf = it + 2;
        if (pf < NIT) ISSUE(pf % 3, pf * KT);
        asm volatile("cp.async.commit_group;" ::: "memory");

        const uint16_t* S = gsm + (it % 3) * STG_U16;
        const uint16_t* sAh = S;
        const uint16_t* sAl = S + 2048;
        const uint16_t* sBh = S + 4096;
        const uint16_t* sBl = S + 6144;
        const int kb = 2 * tg;

        uint32_t ah[2][4], al[2][4];
#pragma unroll
        for (int mt = 0; mt < 2; mt++) {
            int m0 = wm * 32 + mt * 16;
            ah[mt][0] = *(const uint32_t*)(sAh + (m0 + g) * 16 + kb);
            ah[mt][1] = *(const uint32_t*)(sAh + (m0 + g + 8) * 16 + kb);
            ah[mt][2] = *(const uint32_t*)(sAh + (m0 + g) * 16 + kb + 8);
            ah[mt][3] = *(const uint32_t*)(sAh + (m0 + g + 8) * 16 + kb + 8);
            al[mt][0] = *(const uint32_t*)(sAl + (m0 + g) * 16 + kb);
            al[mt][1] = *(const uint32_t*)(sAl + (m0 + g + 8) * 16 + kb);
            al[mt][2] = *(const uint32_t*)(sAl + (m0 + g) * 16 + kb + 8);
            al[mt][3] = *(const uint32_t*)(sAl + (m0 + g + 8) * 16 + kb + 8);
        }
#pragma unroll
        for (int nt = 0; nt < 8; nt++) {
            int n0 = wn * 64 + nt * 8;
            uint32_t bh[2], bl[2];
            bh[0] = *(const uint32_t*)(sBh + (n0 + g) * 16 + kb);
            bh[1] = *(const uint32_t*)(sBh + (n0 + g) * 16 + kb + 8);
            bl[0] = *(const uint32_t*)(sBl + (n0 + g) * 16 + kb);
            bl[1] = *(const uint32_t*)(sBl + (n0 + g) * 16 + kb + 8);
#pragma unroll
            for (int mt = 0; mt < 2; mt++) {
                mma16(acc[mt][nt], ah[mt], bh);
                mma16(acc[mt][nt], ah[mt], bl);
                mma16(acc[mt][nt], al[mt], bh);
            }
        }
    }
#undef ISSUE

    float* outp;
    int noff, Nl;
    if (bn < 16)      { outp = g_xgf;  noff = 0;    Nl = 2048; }
    else if (bn < 32) { outp = g_xgb;  noff = 2048; Nl = 2048; }
    else              { outp = g_skip; noff = 4096; Nl = 1024; }

#pragma unroll
    for (int mt = 0; mt < 2; mt++) {
        int m0 = bm * 128 + wm * 32 + mt * 16 + g;
#pragma unroll
        for (int nt = 0; nt < 8; nt++) {
            int ng = bn * 128 + wn * 64 + nt * 8 + 2 * tg;
            float bias0 = g_biasc[ng], bias1 = g_biasc[ng + 1];
            int nl = ng - noff;
#pragma unroll
            for (int half = 0; half < 2; half++) {
                int m = m0 + half * 8;
                int tt = m >> 5, bb = m & 31;
                size_t base = (size_t)tt * Nl * Bz + (size_t)nl * Bz + bb;
                outp[base]      = acc[mt][nt][half * 2 + 0] + bias0;
                outp[base + Bz] = acc[mt][nt][half * 2 + 1] + bias1;
            }
        }
    }
}

// ---------------- persistent bf16 tensor-core bidirectional LSTM ----------------
// Direct-LDG A-fragments; per-warp wait on the warp's 8 producer blocks only.
#define SM_LSTM_BYTES (8 * 32 * 36 * 4)

__global__ __launch_bounds__(256, 1) void lstm_mma(
    const float* __restrict__ Whf,
    const float* __restrict__ Whb,
    const float* __restrict__ alphas)
{
    extern __shared__ float gs[];   // [8][32][36]

    const int bid = blockIdx.x;
    const int dir = (bid >= 64) ? 1 : 0;
    const int blk = dir ? bid - 64 : bid;
    const float* Wh = dir ? Whb : Whf;
    const float* xg = dir ? g_xgb : g_xgf;
    float* hs = dir ? g_hsb : g_hsf;
    int* flags = g_flag + dir * 64;

    const int tid = threadIdx.x;
    const int wid = tid >> 5, lane = tid & 31;
    const int g = lane >> 2, tg = lane & 3;
    const int cb = tid & 31;
    const int cjl = tid >> 5;
    const int cj = blk * 8 + cjl;

    // fixed fragment-slot of this thread's h element (k=cj, row=cb)
    const int kk = cj & 15, kt_own = cj >> 4;
    const int ro = cb & 15, mt_own = cb >> 4;
    const int reg_own = ((ro >= 8) ? 1 : 0) + ((kk >= 8) ? 2 : 0);
    const int ln_own = (ro & 7) * 4 + ((kk >> 1) & 3);
    const int widx = ((mt_own * 32 + kt_own) * 32 + ln_own) * 4 + reg_own;
    const int half_own = kk & 1;

    // this warp's producer flag (warp w consumes k=64w..64w+63 from blocks 8w..8w+7)
    const int* myflag = &flags[wid * 8 + (lane & 7)];

    // ---- preload Wh fragments (hi/lo, packed bf16x2 along k) ----
    float whi[4][4][2], wlo[4][4][2];
#pragma unroll
    for (int nt = 0; nt < 4; nt++) {
        int n = nt * 8 + g;
        int gate = n & 3, jl = n >> 2;
        int col = gate * 512 + blk * 8 + jl;
#pragma unroll
        for (int ktl = 0; ktl < 4; ktl++) {
            int kt = wid * 4 + ktl;
#pragma unroll
            for (int r = 0; r < 2; r++) {
                int k = kt * 16 + r * 8 + 2 * tg;
                float w0 = Wh[(size_t)k * 2048 + col];
                float w1 = Wh[(size_t)(k + 1) * 2048 + col];
                __nv_bfloat16 h0, l0, h1, l1;
                bsplit(w0, h0, l0);
                bsplit(w1, h1, l1);
                whi[nt][ktl][r] = __uint_as_float(bpack(h0, h1));
                wlo[nt][ktl][r] = __uint_as_float(bpack(l0, l1));
            }
        }
    }

    float cst = 0.f, hprev = 0.f;

    for (int s = 0; s < SL; s++) {
        const int t = dir ? (SL - 1 - s) : s;

        // prefetch xg gates + alpha (independent of h)
        const size_t xb = (size_t)t * (2048 * Bz) + cb;
        float xi = xg[xb + (size_t)(0 * 512 + cj) * Bz];
        float xf = xg[xb + (size_t)(1 * 512 + cj) * Bz];
        float xv = xg[xb + (size_t)(2 * 512 + cj) * Bz];
        float xo = xg[xb + (size_t)(3 * 512 + cj) * Bz];
        float a  = alphas[cb * SL + t];

        float pi = 0.f, pf = 0.f, pg = 0.f, po = 0.f;

        if (s > 0) {
            // per-warp wait: only this warp's 8 producers
            for (;;) {
                int v = (lane < 8) ? ld_acq_i(myflag) : 0x7fffffff;
                if (__all_sync(0xffffffffu, v >= s)) break;
                __nanosleep(16);
            }

            // load A-fragments straight from L2 (frag-layout broadcast buffer)
            const size_t pbase = (size_t)(dir * 2 + ((s - 1) & 1)) * 8192;
            const uint4* fhp = (const uint4*)(g_hbh + pbase);
            const uint4* flp = (const uint4*)(g_hbl + pbase);
            uint4 fh[2][4], fl[2][4];
#pragma unroll
            for (int mt = 0; mt < 2; mt++)
#pragma unroll
                for (int ktl = 0; ktl < 4; ktl++) {
                    int kt = wid * 4 + ktl;
                    fh[mt][ktl] = __ldcg(fhp + (mt * 32 + kt) * 32 + lane);
                    fl[mt][ktl] = __ldcg(flp + (mt * 32 + kt) * 32 + lane);
                }

            float acc[2][4][4];
#pragma unroll
            for (int mt = 0; mt < 2; mt++)
#pragma unroll
                for (int nt = 0; nt < 4; nt++)
#pragma unroll
                    for (int i = 0; i < 4; i++) acc[mt][nt][i] = 0.f;

#pragma unroll
            for (int ktl = 0; ktl < 4; ktl++) {
                uint32_t ah[2][4], al[2][4];
#pragma unroll
                for (int mt = 0; mt < 2; mt++) {
                    ah[mt][0] = fh[mt][ktl].x; ah[mt][1] = fh[mt][ktl].y;
                    ah[mt][2] = fh[mt][ktl].z; ah[mt][3] = fh[mt][ktl].w;
                    al[mt][0] = fl[mt][ktl].x; al[mt][1] = fl[mt][ktl].y;
                    al[mt][2] = fl[mt][ktl].z; al[mt][3] = fl[mt][ktl].w;
                }
#pragma unroll
                for (int nt = 0; nt < 4; nt++) {
                    uint32_t bh[2] = { __float_as_uint(whi[nt][ktl][0]),
                                       __float_as_uint(whi[nt][ktl][1]) };
                    uint32_t bl[2] = { __float_as_uint(wlo[nt][ktl][0]),
                                       __float_as_uint(wlo[nt][ktl][1]) };
#pragma unroll
                    for (int mt = 0; mt < 2; mt++) {
                        mma16(acc[mt][nt], ah[mt], bh);
                        mma16(acc[mt][nt], ah[mt], bl);
                        mma16(acc[mt][nt], al[mt], bh);
                    }
                }
            }

            // write partial gate sums: gs[wid][b][n]
#pragma unroll
            for (int mt = 0; mt < 2; mt++) {
#pragma unroll
                for (int nt = 0; nt < 4; nt++) {
                    int row0 = mt * 16 + g;
                    int col = nt * 8 + 2 * tg;
                    int b0i = (wid * 32 + row0) * 36 + col;
                    gs[b0i]     = acc[mt][nt][0];
                    gs[b0i + 1] = acc[mt][nt][1];
                    int b1i = (wid * 32 + row0 + 8) * 36 + col;
                    gs[b1i]     = acc[mt][nt][2];
                    gs[b1i + 1] = acc[mt][nt][3];
                }
            }
            __syncthreads();

#pragma unroll
            for (int w = 0; w < 8; w++) {
                int base = (w * 32 + cb) * 36 + cjl * 4;
                pi += gs[base + 0];
                pf += gs[base + 1];
                pg += gs[base + 2];
                po += gs[base + 3];
            }
        }

        // LSTM cell
        float gi = sigm_f(pi + xi);
        float gf = sigm_f(pf + xf);
        float gG = tanh_f(pg + xv);
        float go = sigm_f(po + xo);

        float cn = gf * cst + gi * gG;
        float hn = go * tanh_f(cn);

        cst = a * cn + (1.f - a) * cst;
        float h2 = a * hn + (1.f - a) * hprev;
        hprev = h2;

        hs[(size_t)t * (HD * Bz) + cj * 32 + cb] = h2;

        // publish h in frag layout, pre-split bf16 hi/lo
        {
            __nv_bfloat16 hi, lo;
            bsplit(h2, hi, lo);
            size_t pbase = (size_t)(dir * 2 + (s & 1)) * 8192;
            ((__nv_bfloat16*)(g_hbh + pbase))[widx * 2 + half_own] = hi;
            ((__nv_bfloat16*)(g_hbl + pbase))[widx * 2 + half_own] = lo;
        }

        __threadfence();
        __syncthreads();
        if (tid == 0) st_rel_i(&flags[blk], s + 1);
    }
}

// ---------------- pooling ----------------
__global__ void pool_kernel(const float* __restrict__ alphas, float* __restrict__ out)
{
    const int tid = blockIdx.x * blockDim.x + threadIdx.x;
    const int b = tid & 31;
    const int g = tid >> 5;
    if (g >= 1024) return;

    const float* top = (g < HD) ? (g_hsf + (size_t)g * 32 + b)
                                : (g_hsb + (size_t)(g - HD) * 32 + b);
    const float* sk = g_skip + (size_t)g * 32 + b;

    float sum = 0.f, asum = 0.f, mx = -INFINITY;
    for (int t = 0; t < SL; t++) {
        float a = alphas[b * SL + t];
        float r = (top[(size_t)t * (HD * Bz)] + sk[(size_t)t * (1024 * Bz)]) * a;
        sum += r;
        asum += a;
        if (a > 0.f) mx = fmaxf(mx, r);
    }
    float mean = sum / (asum + 1e-6f);
    if (isinf(mx)) mx = 0.f;
    out[b * 2048 + g] = mean;
    out[b * 2048 + 1024 + g] = mx;
}

// ---------------- launch ----------------
extern "C" void kernel_launch(void* const* d_in, const int* in_sizes, int n_in,
                              void* d_out, int out_size)
{
    const float* values = (const float*)d_in[0];
    const float* alphas = (const float*)d_in[1];
    const float* Wx_f = (const float*)d_in[2];
    const float* Wh_f = (const float*)d_in[3];
    const float* b_f  = (const float*)d_in[4];
    const float* Wx_b = (const float*)d_in[5];
    const float* Wh_b = (const float*)d_in[6];
    const float* b_b  = (const float*)d_in[7];
    const float* Ws   = (const float*)d_in[8];
    const float* bs   = (const float*)d_in[9];
    float* out = (float*)d_out;

    cudaFuncSetAttribute(gemm_mma, cudaFuncAttributeMaxDynamicSharedMemorySize, 49152);
    cudaFuncSetAttribute(lstm_mma, cudaFuncAttributeMaxDynamicSharedMemorySize, SM_LSTM_BYTES);

    init_misc<<<20, 256>>>(b_f, b_b, bs);
    split_A<<<Bz * SL, 256>>>(values);
    split_W<<<dim3(VD / 32, NT / 32), 256>>>(Wx_f, Wx_b, Ws);
    gemm_mma<<<dim3(NT / 128, (Bz * SL) / 128), 256, 49152>>>();
    lstm_mma<<<NBLK, 256, SM_LSTM_BYTES>>>(Wh_f, Wh_b, alphas);
    pool_kernel<<<(Bz * 1024) / 256, 256>>>(alphas, out);
}

// round 11
// speedup vs baseline: 2.0357x; 2.0357x over previous
// R10: recurrence reverted to R8 wait protocol (128 spinners, not 1024 — R9's per-warp
// wait caused L2 flag-line contention, 2x regression) + tid0-only release fence.
// GEMM: cp.async 3-stage k16 pipeline with 24-u16 padded rows (conflict-free frag LDS).
#include <cuda_runtime.h>
#include <cuda_bf16.h>
#include <math.h>
#include <stdint.h>

#define Bz 32
#define SL 512
#define VD 768
#define HD 512
#define NT 5120     // fused N: 2048 (Wx_f) + 2048 (Wx_b) + 1024 (Ws)
#define NBLK 128    // 64 fwd + 64 bwd persistent blocks

// ---------------- scratch (device globals; no allocation allowed) ----------------
__device__ __align__(16) float g_xgf[(size_t)SL * 2048 * Bz];   // [t][g][b]
__device__ __align__(16) float g_xgb[(size_t)SL * 2048 * Bz];   // [t][g][b]
__device__ __align__(16) float g_skip[(size_t)SL * 1024 * Bz];  // [t][g][b]
__device__ __align__(16) float g_hsf[(size_t)SL * HD * Bz];     // [t][j][b]
__device__ __align__(16) float g_hsb[(size_t)SL * HD * Bz];     // [t][j][b]
// h broadcast in A-fragment layout, bf16 hi/lo planes: [dir][parity][8192 u32]
__device__ __align__(16) uint32_t g_hbh[2 * 2 * 8192];
__device__ __align__(16) uint32_t g_hbl[2 * 2 * 8192];
__device__ int g_flag[NBLK];

// bf16-split GEMM operands
__device__ __align__(16) __nv_bfloat16 g_Ah[(size_t)(Bz * SL) * VD];  // [m][k]
__device__ __align__(16) __nv_bfloat16 g_Al[(size_t)(Bz * SL) * VD];
__device__ __align__(16) __nv_bfloat16 g_Wth[(size_t)NT * VD];        // W^T [n][k]
__device__ __align__(16) __nv_bfloat16 g_Wtl[(size_t)NT * VD];
__device__ __align__(16) float g_biasc[NT];

// ---------------- helpers ----------------
__device__ __forceinline__ void bsplit(float x, __nv_bfloat16& hi, __nv_bfloat16& lo) {
    hi = __float2bfloat16_rn(x);
    lo = __float2bfloat16_rn(x - __bfloat162float(hi));
}
__device__ __forceinline__ uint32_t bpack(__nv_bfloat16 a, __nv_bfloat16 b) {
    uint16_t ua = *(uint16_t*)&a, ub = *(uint16_t*)&b;
    return (uint32_t)ua | ((uint32_t)ub << 16);
}
__device__ __forceinline__ void mma16(float* d, const uint32_t* a, const uint32_t* b) {
    asm volatile(
        "mma.sync.aligned.m16n8k16.row.col.f32.bf16.bf16.f32 "
        "{%0,%1,%2,%3}, {%4,%5,%6,%7}, {%8,%9}, {%0,%1,%2,%3};"
        : "+f"(d[0]), "+f"(d[1]), "+f"(d[2]), "+f"(d[3])
        : "r"(a[0]), "r"(a[1]), "r"(a[2]), "r"(a[3]), "r"(b[0]), "r"(b[1]));
}
__device__ __forceinline__ int ld_acq_i(const int* p) {
    int v;
    asm volatile("ld.acquire.gpu.s32 %0, [%1];" : "=r"(v) : "l"(p) : "memory");
    return v;
}
__device__ __forceinline__ void st_rel_i(int* p, int v) {
    asm volatile("st.release.gpu.s32 [%0], %1;" :: "l"(p), "r"(v) : "memory");
}
__device__ __forceinline__ void cp16(uint32_t dst, const void* src) {
    asm volatile("cp.async.cg.shared.global [%0], [%1], 16;" :: "r"(dst), "l"(src));
}
__device__ __forceinline__ uint32_t smem_u32(const void* p) {
    uint32_t a;
    asm("{ .reg .u64 t; cvta.to.shared.u64 t, %1; cvt.u32.u64 %0, t; }" : "=r"(a) : "l"(p));
    return a;
}
__device__ __forceinline__ float sigm_f(float x) { return __fdividef(1.f, 1.f + __expf(-x)); }
__device__ __forceinline__ float tanh_f(float x) { return __fdividef(2.f, 1.f + __expf(-2.f * x)) - 1.f; }

// ---------------- init: flags + bias concat ----------------
__global__ void init_misc(const float* __restrict__ bf, const float* __restrict__ bb_,
                          const float* __restrict__ bs) {
    int c = blockIdx.x * 256 + threadIdx.x;
    if (c < NT)
        g_biasc[c] = (c < 2048) ? bf[c] : (c < 4096) ? bb_[c - 2048] : bs[c - 4096];
    if (blockIdx.x == 0 && threadIdx.x < NBLK) g_flag[threadIdx.x] = 0;
}

// ---------------- split A (values -> bf16 hi/lo planes, [m][k]) ----------------
__global__ void split_A(const float* __restrict__ values) {
    const int m = blockIdx.x;              // m = t*32 + b
    const int b = m & 31, t = m >> 5;
    const float* src = values + ((size_t)b * SL + t) * VD;
    for (int v = threadIdx.x; v < VD; v += 256) {
        __nv_bfloat16 hi, lo;
        bsplit(src[v], hi, lo);
        g_Ah[(size_t)m * VD + v] = hi;
        g_Al[(size_t)m * VD + v] = lo;
    }
}

// ---------------- split + transpose W -> [n][k] bf16 hi/lo ----------------
__global__ void split_W(const float* __restrict__ Wxf, const float* __restrict__ Wxb,
                        const float* __restrict__ Ws) {
    __shared__ float tile[32][33];
    const int k0 = blockIdx.x * 32;
    const int n0 = blockIdx.y * 32;
    const int tid = threadIdx.x;
    const int c = tid & 31;
    for (int r = tid >> 5; r < 32; r += 8) {
        int k = k0 + r, n = n0 + c;
        float x = (n < 2048) ? Wxf[(size_t)k * 2048 + n]
                : (n < 4096) ? Wxb[(size_t)k * 2048 + (n - 2048)]
                             : Ws[(size_t)k * 1024 + (n - 4096)];
        tile[r][c] = x;
    }
    __syncthreads();
    for (int r = tid >> 5; r < 32; r += 8) {
        int n = n0 + r, k = k0 + c;
        __nv_bfloat16 hi, lo;
        bsplit(tile[c][r], hi, lo);
        g_Wth[(size_t)n * VD + k] = hi;
        g_Wtl[(size_t)n * VD + k] = lo;
    }
}

// ---------------- fused bf16 3-chain GEMM, cp.async 3-stage, padded rows ----------------
// k-tile 16, 48 iters. Row = 24 u16 (16 data + 8 pad, 48B): conflict-free frag LDS,
// 16B-aligned cp.async chunks. Stage = 4 planes * 128*24*2B = 24KB; 3 stages = 72KB.
#define KT 16
#define NIT (VD / KT)          // 48
#define PSTR 24                // padded row stride, u16
#define PLANE_U16 (128 * PSTR) // 3072
#define STG_U16 (4 * PLANE_U16)
__global__ __launch_bounds__(256, 2) void gemm_mma()
{
    extern __shared__ uint16_t gsm[];   // 3 * STG_U16

    const int bn = blockIdx.x, bm = blockIdx.y;
    const int tid = threadIdx.x;
    const int wid = tid >> 5, lane = tid & 31;
    const int wm = wid & 3, wn = wid >> 2;
    const int g = lane >> 2, tg = lane & 3;

    float acc[2][8][4];
#pragma unroll
    for (int mt = 0; mt < 2; mt++)
#pragma unroll
        for (int nt = 0; nt < 8; nt++)
#pragma unroll
            for (int i = 0; i < 4; i++) acc[mt][nt][i] = 0.f;

    // cp.async mapping: thread -> one 16B chunk per plane per k-tile
    const int prow = tid >> 1;                 // 0..127
    const int pk = (tid & 1) * 8;              // u16 offset within k-tile row
    const __nv_bfloat16* srcAh = g_Ah + (size_t)(bm * 128 + prow) * VD + pk;
    const __nv_bfloat16* srcAl = g_Al + (size_t)(bm * 128 + prow) * VD + pk;
    const __nv_bfloat16* srcBh = g_Wth + (size_t)(bn * 128 + prow) * VD + pk;
    const __nv_bfloat16* srcBl = g_Wtl + (size_t)(bn * 128 + prow) * VD + pk;
    const uint32_t dbase = smem_u32(gsm) + (prow * PSTR + pk) * 2;   // byte addr

#define ISSUE(st, k0) do {                              \
        uint32_t d = dbase + (st) * (STG_U16 * 2);      \
        cp16(d,                       srcAh + (k0));    \
        cp16(d + PLANE_U16 * 2,       srcAl + (k0));    \
        cp16(d + PLANE_U16 * 4,       srcBh + (k0));    \
        cp16(d + PLANE_U16 * 6,       srcBl + (k0));    \
    } while (0)

    ISSUE(0, 0);
    asm volatile("cp.async.commit_group;" ::: "memory");
    ISSUE(1, KT);
    asm volatile("cp.async.commit_group;" ::: "memory");

    for (int it = 0; it < NIT; it++) {
        asm volatile("cp.async.wait_group 1;" ::: "memory");
        __syncthreads();   // loads of `it` visible; compute of `it-1` done (buffer reuse safe)

        int pf = it + 2;
        if (pf < NIT) ISSUE(pf % 3, pf * KT);
        asm volatile("cp.async.commit_group;" ::: "memory");

        const uint16_t* S = gsm + (it % 3) * STG_U16;
        const uint16_t* sAh = S;
        const uint16_t* sAl = S + PLANE_U16;
        const uint16_t* sBh = S + 2 * PLANE_U16;
        const uint16_t* sBl = S + 3 * PLANE_U16;
        const int kb = 2 * tg;

        uint32_t ah[2][4], al[2][4];
#pragma unroll
        for (int mt = 0; mt < 2; mt++) {
            int m0 = wm * 32 + mt * 16;
            ah[mt][0] = *(const uint32_t*)(sAh + (m0 + g) * PSTR + kb);
            ah[mt][1] = *(const uint32_t*)(sAh + (m0 + g + 8) * PSTR + kb);
            ah[mt][2] = *(const uint32_t*)(sAh + (m0 + g) * PSTR + kb + 8);
            ah[mt][3] = *(const uint32_t*)(sAh + (m0 + g + 8) * PSTR + kb + 8);
            al[mt][0] = *(const uint32_t*)(sAl + (m0 + g) * PSTR + kb);
            al[mt][1] = *(const uint32_t*)(sAl + (m0 + g + 8) * PSTR + kb);
            al[mt][2] = *(const uint32_t*)(sAl + (m0 + g) * PSTR + kb + 8);
            al[mt][3] = *(const uint32_t*)(sAl + (m0 + g + 8) * PSTR + kb + 8);
        }
#pragma unroll
        for (int nt = 0; nt < 8; nt++) {
            int n0 = wn * 64 + nt * 8;
            uint32_t bh[2], bl[2];
            bh[0] = *(const uint32_t*)(sBh + (n0 + g) * PSTR + kb);
            bh[1] = *(const uint32_t*)(sBh + (n0 + g) * PSTR + kb + 8);
            bl[0] = *(const uint32_t*)(sBl + (n0 + g) * PSTR + kb);
            bl[1] = *(const uint32_t*)(sBl + (n0 + g) * PSTR + kb + 8);
#pragma unroll
            for (int mt = 0; mt < 2; mt++) {
                mma16(acc[mt][nt], ah[mt], bh);
                mma16(acc[mt][nt], ah[mt], bl);
                mma16(acc[mt][nt], al[mt], bh);
            }
        }
    }
#undef ISSUE

    float* outp;
    int noff, Nl;
    if (bn < 16)      { outp = g_xgf;  noff = 0;    Nl = 2048; }
    else if (bn < 32) { outp = g_xgb;  noff = 2048; Nl = 2048; }
    else              { outp = g_skip; noff = 4096; Nl = 1024; }

#pragma unroll
    for (int mt = 0; mt < 2; mt++) {
        int m0 = bm * 128 + wm * 32 + mt * 16 + g;
#pragma unroll
        for (int nt = 0; nt < 8; nt++) {
            int ng = bn * 128 + wn * 64 + nt * 8 + 2 * tg;
            float bias0 = g_biasc[ng], bias1 = g_biasc[ng + 1];
            int nl = ng - noff;
#pragma unroll
            for (int half = 0; half < 2; half++) {
                int m = m0 + half * 8;
                int tt = m >> 5, bb = m & 31;
                size_t base = (size_t)tt * Nl * Bz + (size_t)nl * Bz + bb;
                outp[base]      = acc[mt][nt][half * 2 + 0] + bias0;
                outp[base + Bz] = acc[mt][nt][half * 2 + 1] + bias1;
            }
        }
    }
}

// ---------------- persistent bf16 tensor-core bidirectional LSTM ----------------
// R8 protocol: warp 0 waits on all 64 producer flags, one syncthreads, direct-LDG frags.
#define SM_LSTM_BYTES (8 * 32 * 36 * 4)

__global__ __launch_bounds__(256, 1) void lstm_mma(
    const float* __restrict__ Whf,
    const float* __restrict__ Whb,
    const float* __restrict__ alphas)
{
    extern __shared__ float gs[];   // [8][32][36]

    const int bid = blockIdx.x;
    const int dir = (bid >= 64) ? 1 : 0;
    const int blk = dir ? bid - 64 : bid;
    const float* Wh = dir ? Whb : Whf;
    const float* xg = dir ? g_xgb : g_xgf;
    float* hs = dir ? g_hsb : g_hsf;
    int* flags = g_flag + dir * 64;

    const int tid = threadIdx.x;
    const int wid = tid >> 5, lane = tid & 31;
    const int g = lane >> 2, tg = lane & 3;
    const int cb = tid & 31;
    const int cjl = tid >> 5;
    const int cj = blk * 8 + cjl;

    // fixed fragment-slot of this thread's h element (k=cj, row=cb)
    const int kk = cj & 15, kt_own = cj >> 4;
    const int ro = cb & 15, mt_own = cb >> 4;
    const int reg_own = ((ro >= 8) ? 1 : 0) + ((kk >= 8) ? 2 : 0);
    const int ln_own = (ro & 7) * 4 + ((kk >> 1) & 3);
    const int widx = ((mt_own * 32 + kt_own) * 32 + ln_own) * 4 + reg_own;
    const int half_own = kk & 1;

    // ---- preload Wh fragments (hi/lo, packed bf16x2 along k) ----
    float whi[4][4][2], wlo[4][4][2];
#pragma unroll
    for (int nt = 0; nt < 4; nt++) {
        int n = nt * 8 + g;
        int gate = n & 3, jl = n >> 2;
        int col = gate * 512 + blk * 8 + jl;
#pragma unroll
        for (int ktl = 0; ktl < 4; ktl++) {
            int kt = wid * 4 + ktl;
#pragma unroll
            for (int r = 0; r < 2; r++) {
                int k = kt * 16 + r * 8 + 2 * tg;
                float w0 = Wh[(size_t)k * 2048 + col];
                float w1 = Wh[(size_t)(k + 1) * 2048 + col];
                __nv_bfloat16 h0, l0, h1, l1;
                bsplit(w0, h0, l0);
                bsplit(w1, h1, l1);
                whi[nt][ktl][r] = __uint_as_float(bpack(h0, h1));
                wlo[nt][ktl][r] = __uint_as_float(bpack(l0, l1));
            }
        }
    }

    float cst = 0.f, hprev = 0.f;

    for (int s = 0; s < SL; s++) {
        const int t = dir ? (SL - 1 - s) : s;

        // prefetch xg gates + alpha (independent of h)
        const size_t xb = (size_t)t * (2048 * Bz) + cb;
        float xi = xg[xb + (size_t)(0 * 512 + cj) * Bz];
        float xf = xg[xb + (size_t)(1 * 512 + cj) * Bz];
        float xv = xg[xb + (size_t)(2 * 512 + cj) * Bz];
        float xo = xg[xb + (size_t)(3 * 512 + cj) * Bz];
        float a  = alphas[cb * SL + t];

        float pi = 0.f, pf = 0.f, pg = 0.f, po = 0.f;

        if (s > 0) {
            // wait for all 64 producers of this direction (warp 0 only spins)
            if (wid == 0) {
                for (;;) {
                    int v1 = ld_acq_i(&flags[lane]);
                    int v2 = ld_acq_i(&flags[lane + 32]);
                    if (__all_sync(0xffffffffu, (v1 >= s) && (v2 >= s))) break;
                    __nanosleep(20);
                }
            }
            __syncthreads();

            // load A-fragments straight from L2 (frag-layout broadcast buffer)
            const size_t pbase = (size_t)(dir * 2 + ((s - 1) & 1)) * 8192;
            const uint4* fhp = (const uint4*)(g_hbh + pbase);
            const uint4* flp = (const uint4*)(g_hbl + pbase);
            uint4 fh[2][4], fl[2][4];
#pragma unroll
            for (int mt = 0; mt < 2; mt++)
#pragma unroll
                for (int ktl = 0; ktl < 4; ktl++) {
                    int kt = wid * 4 + ktl;
                    fh[mt][ktl] = __ldcg(fhp + (mt * 32 + kt) * 32 + lane);
                    fl[mt][ktl] = __ldcg(flp + (mt * 32 + kt) * 32 + lane);
                }

            float acc[2][4][4];
#pragma unroll
            for (int mt = 0; mt < 2; mt++)
#pragma unroll
                for (int nt = 0; nt < 4; nt++)
#pragma unroll
                    for (int i = 0; i < 4; i++) acc[mt][nt][i] = 0.f;

#pragma unroll
            for (int ktl = 0; ktl < 4; ktl++) {
                uint32_t ah[2][4], al[2][4];
#pragma unroll
                for (int mt = 0; mt < 2; mt++) {
                    ah[mt][0] = fh[mt][ktl].x; ah[mt][1] = fh[mt][ktl].y;
                    ah[mt][2] = fh[mt][ktl].z; ah[mt][3] = fh[mt][ktl].w;
                    al[mt][0] = fl[mt][ktl].x; al[mt][1] = fl[mt][ktl].y;
                    al[mt][2] = fl[mt][ktl].z; al[mt][3] = fl[mt][ktl].w;
                }
#pragma unroll
                for (int nt = 0; nt < 4; nt++) {
                    uint32_t bh[2] = { __float_as_uint(whi[nt][ktl][0]),
                                       __float_as_uint(whi[nt][ktl][1]) };
                    uint32_t bl[2] = { __float_as_uint(wlo[nt][ktl][0]),
                                       __float_as_uint(wlo[nt][ktl][1]) };
#pragma unroll
                    for (int mt = 0; mt < 2; mt++) {
                        mma16(acc[mt][nt], ah[mt], bh);
                        mma16(acc[mt][nt], ah[mt], bl);
                        mma16(acc[mt][nt], al[mt], bh);
                    }
                }
            }

            // write partial gate sums: gs[wid][b][n]
#pragma unroll
            for (int mt = 0; mt < 2; mt++) {
#pragma unroll
                for (int nt = 0; nt < 4; nt++) {
                    int row0 = mt * 16 + g;
                    int col = nt * 8 + 2 * tg;
                    int b0i = (wid * 32 + row0) * 36 + col;
                    gs[b0i]     = acc[mt][nt][0];
                    gs[b0i + 1] = acc[mt][nt][1];
                    int b1i = (wid * 32 + row0 + 8) * 36 + col;
                    gs[b1i]     = acc[mt][nt][2];
                    gs[b1i + 1] = acc[mt][nt][3];
                }
            }
            __syncthreads();

#pragma unroll
            for (int w = 0; w < 8; w++) {
                int base = (w * 32 + cb) * 36 + cjl * 4;
                pi += gs[base + 0];
                pf += gs[base + 1];
                pg += gs[base + 2];
                po += gs[base + 3];
            }
        }

        // LSTM cell
        float gi = sigm_f(pi + xi);
        float gf = sigm_f(pf + xf);
        float gG = tanh_f(pg + xv);
        float go = sigm_f(po + xo);

        float cn = gf * cst + gi * gG;
        float hn = go * tanh_f(cn);

        cst = a * cn + (1.f - a) * cst;
        float h2 = a * hn + (1.f - a) * hprev;
        hprev = h2;

        hs[(size_t)t * (HD * Bz) + cj * 32 + cb] = h2;

        // publish h in frag layout, pre-split bf16 hi/lo
        {
            __nv_bfloat16 hi, lo;
            bsplit(h2, hi, lo);
            size_t pb = (size_t)(dir * 2 + (s & 1)) * 8192;
            ((__nv_bfloat16*)(g_hbh + pb))[widx * 2 + half_own] = hi;
            ((__nv_bfloat16*)(g_hbl + pb))[widx * 2 + half_own] = lo;
        }

        __syncthreads();
        if (tid == 0) { __threadfence(); st_rel_i(&flags[blk], s + 1); }
    }
}

// ---------------- pooling ----------------
__global__ void pool_kernel(const float* __restrict__ alphas, float* __restrict__ out)
{
    const int tid = blockIdx.x * blockDim.x + threadIdx.x;
    const int b = tid & 31;
    const int g = tid >> 5;
    if (g >= 1024) return;

    const float* top = (g < HD) ? (g_hsf + (size_t)g * 32 + b)
                                : (g_hsb + (size_t)(g - HD) * 32 + b);
    const float* sk = g_skip + (size_t)g * 32 + b;

    float sum = 0.f, asum = 0.f, mx = -INFINITY;
    for (int t = 0; t < SL; t++) {
        float a = alphas[b * SL + t];
        float r = (top[(size_t)t * (HD * Bz)] + sk[(size_t)t * (1024 * Bz)]) * a;
        sum += r;
        asum += a;
        if (a > 0.f) mx = fmaxf(mx, r);
    }
    float mean = sum / (asum + 1e-6f);
    if (isinf(mx)) mx = 0.f;
    out[b * 2048 + g] = mean;
    out[b * 2048 + 1024 + g] = mx;
}

// ---------------- launch ----------------
extern "C" void kernel_launch(void* const* d_in, const int* in_sizes, int n_in,
                              void* d_out, int out_size)
{
    const float* values = (const float*)d_in[0];
    const float* alphas = (const float*)d_in[1];
    const float* Wx_f = (const float*)d_in[2];
    const float* Wh_f = (const float*)d_in[3];
    const float* b_f  = (const float*)d_in[4];
    const float* Wx_b = (const float*)d_in[5];
    const float* Wh_b = (const float*)d_in[6];
    const float* b_b  = (const float*)d_in[7];
    const float* Ws   = (const float*)d_in[8];
    const float* bs   = (const float*)d_in[9];
    float* out = (float*)d_out;

    cudaFuncSetAttribute(gemm_mma, cudaFuncAttributeMaxDynamicSharedMemorySize, 73728);
    cudaFuncSetAttribute(lstm_mma, cudaFuncAttributeMaxDynamicSharedMemorySize, SM_LSTM_BYTES);

    init_misc<<<20, 256>>>(b_f, b_b, bs);
    split_A<<<Bz * SL, 256>>>(values);
    split_W<<<dim3(VD / 32, NT / 32), 256>>>(Wx_f, Wx_b, Ws);
    gemm_mma<<<dim3(NT / 128, (Bz * SL) / 128), 256, 73728>>>();
    lstm_mma<<<NBLK, 256, SM_LSTM_BYTES>>>(Wh_f, Wh_b, alphas);
    pool_kernel<<<(Bz * 1024) / 256, 256>>>(alphas, out);
}

// round 13
// speedup vs baseline: 2.1615x; 1.0618x over previous
// R11: (1) GEMM reverted to R8 blocking version (both cp.async variants measured neutral/worse);
// (2) recurrence drops the h-lo broadcast plane: gate preact = W(hi+lo) x round_bf16(h).
// Halves per-step L2 broadcast traffic (8->4 MB), mma 96->64/warp. Predicted rel_err ~1e-4.
#include <cuda_runtime.h>
#include <cuda_bf16.h>
#include <math.h>
#include <stdint.h>

#define Bz 32
#define SL 512
#define VD 768
#define HD 512
#define NT 5120     // fused N: 2048 (Wx_f) + 2048 (Wx_b) + 1024 (Ws)
#define NBLK 128    // 64 fwd + 64 bwd persistent blocks

// ---------------- scratch (device globals; no allocation allowed) ----------------
__device__ __align__(16) float g_xgf[(size_t)SL * 2048 * Bz];   // [t][g][b]
__device__ __align__(16) float g_xgb[(size_t)SL * 2048 * Bz];   // [t][g][b]
__device__ __align__(16) float g_skip[(size_t)SL * 1024 * Bz];  // [t][g][b]
__device__ __align__(16) float g_hsf[(size_t)SL * HD * Bz];     // [t][j][b]
__device__ __align__(16) float g_hsb[(size_t)SL * HD * Bz];     // [t][j][b]
// h broadcast in A-fragment layout, bf16 hi plane only: [dir][parity][8192 u32]
__device__ __align__(16) uint32_t g_hbh[2 * 2 * 8192];
__device__ int g_flag[NBLK];

// bf16-split GEMM operands
__device__ __align__(16) __nv_bfloat16 g_Ah[(size_t)(Bz * SL) * VD];  // [m][k]
__device__ __align__(16) __nv_bfloat16 g_Al[(size_t)(Bz * SL) * VD];
__device__ __align__(16) __nv_bfloat16 g_Wth[(size_t)NT * VD];        // W^T [n][k]
__device__ __align__(16) __nv_bfloat16 g_Wtl[(size_t)NT * VD];
__device__ __align__(16) float g_biasc[NT];

// ---------------- helpers ----------------
__device__ __forceinline__ void bsplit(float x, __nv_bfloat16& hi, __nv_bfloat16& lo) {
    hi = __float2bfloat16_rn(x);
    lo = __float2bfloat16_rn(x - __bfloat162float(hi));
}
__device__ __forceinline__ uint32_t bpack(__nv_bfloat16 a, __nv_bfloat16 b) {
    uint16_t ua = *(uint16_t*)&a, ub = *(uint16_t*)&b;
    return (uint32_t)ua | ((uint32_t)ub << 16);
}
__device__ __forceinline__ void mma16(float* d, const uint32_t* a, const uint32_t* b) {
    asm volatile(
        "mma.sync.aligned.m16n8k16.row.col.f32.bf16.bf16.f32 "
        "{%0,%1,%2,%3}, {%4,%5,%6,%7}, {%8,%9}, {%0,%1,%2,%3};"
        : "+f"(d[0]), "+f"(d[1]), "+f"(d[2]), "+f"(d[3])
        : "r"(a[0]), "r"(a[1]), "r"(a[2]), "r"(a[3]), "r"(b[0]), "r"(b[1]));
}
__device__ __forceinline__ int ld_acq_i(const int* p) {
    int v;
    asm volatile("ld.acquire.gpu.s32 %0, [%1];" : "=r"(v) : "l"(p) : "memory");
    return v;
}
__device__ __forceinline__ void st_rel_i(int* p, int v) {
    asm volatile("st.release.gpu.s32 [%0], %1;" :: "l"(p), "r"(v) : "memory");
}
__device__ __forceinline__ float sigm_f(float x) { return __fdividef(1.f, 1.f + __expf(-x)); }
__device__ __forceinline__ float tanh_f(float x) { return __fdividef(2.f, 1.f + __expf(-2.f * x)) - 1.f; }

// ---------------- init: flags + bias concat ----------------
__global__ void init_misc(const float* __restrict__ bf, const float* __restrict__ bb_,
                          const float* __restrict__ bs) {
    int c = blockIdx.x * 256 + threadIdx.x;
    if (c < NT)
        g_biasc[c] = (c < 2048) ? bf[c] : (c < 4096) ? bb_[c - 2048] : bs[c - 4096];
    if (blockIdx.x == 0 && threadIdx.x < NBLK) g_flag[threadIdx.x] = 0;
}

// ---------------- split A (values -> bf16 hi/lo planes, [m][k]) ----------------
__global__ void split_A(const float* __restrict__ values) {
    const int m = blockIdx.x;              // m = t*32 + b
    const int b = m & 31, t = m >> 5;
    const float* src = values + ((size_t)b * SL + t) * VD;
    for (int v = threadIdx.x; v < VD; v += 256) {
        __nv_bfloat16 hi, lo;
        bsplit(src[v], hi, lo);
        g_Ah[(size_t)m * VD + v] = hi;
        g_Al[(size_t)m * VD + v] = lo;
    }
}

// ---------------- split + transpose W -> [n][k] bf16 hi/lo ----------------
__global__ void split_W(const float* __restrict__ Wxf, const float* __restrict__ Wxb,
                        const float* __restrict__ Ws) {
    __shared__ float tile[32][33];
    const int k0 = blockIdx.x * 32;
    const int n0 = blockIdx.y * 32;
    const int tid = threadIdx.x;
    const int c = tid & 31;
    for (int r = tid >> 5; r < 32; r += 8) {
        int k = k0 + r, n = n0 + c;
        float x = (n < 2048) ? Wxf[(size_t)k * 2048 + n]
                : (n < 4096) ? Wxb[(size_t)k * 2048 + (n - 2048)]
                             : Ws[(size_t)k * 1024 + (n - 4096)];
        tile[r][c] = x;
    }
    __syncthreads();
    for (int r = tid >> 5; r < 32; r += 8) {
        int n = n0 + r, k = k0 + c;
        __nv_bfloat16 hi, lo;
        bsplit(tile[c][r], hi, lo);
        g_Wth[(size_t)n * VD + k] = hi;
        g_Wtl[(size_t)n * VD + k] = lo;
    }
}

// ---------------- fused bf16 3-chain GEMM (R8 proven version, k-tile 32) ----------------
#define GSTR 56
__global__ __launch_bounds__(256, 2) void gemm_mma()
{
    extern __shared__ uint16_t gsm[];
    uint16_t* sAh = gsm;
    uint16_t* sAl = gsm + 7168;
    uint16_t* sBh = gsm + 14336;
    uint16_t* sBl = gsm + 21504;

    const int bn = blockIdx.x, bm = blockIdx.y;
    const int tid = threadIdx.x;
    const int wid = tid >> 5, lane = tid & 31;
    const int wm = wid & 3, wn = wid >> 2;
    const int g = lane >> 2, tg = lane & 3;

    float acc[2][8][4];
#pragma unroll
    for (int mt = 0; mt < 2; mt++)
#pragma unroll
        for (int nt = 0; nt < 8; nt++)
#pragma unroll
            for (int i = 0; i < 4; i++) acc[mt][nt][i] = 0.f;

    const int srow = tid >> 2, sq = (tid & 3) * 8;

    for (int k0 = 0; k0 < VD; k0 += 32) {
        __syncthreads();
#pragma unroll
        for (int half = 0; half < 2; half++) {
            int row = srow + half * 64;
            size_t ga = (size_t)(bm * 128 + row) * VD + k0 + sq;
            size_t gb = (size_t)(bn * 128 + row) * VD + k0 + sq;
            *(float4*)(sAh + row * GSTR + sq) = *(const float4*)(g_Ah + ga);
            *(float4*)(sAl + row * GSTR + sq) = *(const float4*)(g_Al + ga);
            *(float4*)(sBh + row * GSTR + sq) = *(const float4*)(g_Wth + gb);
            *(float4*)(sBl + row * GSTR + sq) = *(const float4*)(g_Wtl + gb);
        }
        __syncthreads();

#pragma unroll
        for (int kc = 0; kc < 2; kc++) {
            const int kb = kc * 16 + 2 * tg;
            uint32_t ah[2][4], al[2][4];
#pragma unroll
            for (int mt = 0; mt < 2; mt++) {
                int m0 = wm * 32 + mt * 16;
                ah[mt][0] = *(const uint32_t*)(sAh + (m0 + g) * GSTR + kb);
                ah[mt][1] = *(const uint32_t*)(sAh + (m0 + g + 8) * GSTR + kb);
                ah[mt][2] = *(const uint32_t*)(sAh + (m0 + g) * GSTR + kb + 8);
                ah[mt][3] = *(const uint32_t*)(sAh + (m0 + g + 8) * GSTR + kb + 8);
                al[mt][0] = *(const uint32_t*)(sAl + (m0 + g) * GSTR + kb);
                al[mt][1] = *(const uint32_t*)(sAl + (m0 + g + 8) * GSTR + kb);
                al[mt][2] = *(const uint32_t*)(sAl + (m0 + g) * GSTR + kb + 8);
                al[mt][3] = *(const uint32_t*)(sAl + (m0 + g + 8) * GSTR + kb + 8);
            }
#pragma unroll
            for (int nt = 0; nt < 8; nt++) {
                int n0 = wn * 64 + nt * 8;
                uint32_t bh[2], bl[2];
                bh[0] = *(const uint32_t*)(sBh + (n0 + g) * GSTR + kb);
                bh[1] = *(const uint32_t*)(sBh + (n0 + g) * GSTR + kb + 8);
                bl[0] = *(const uint32_t*)(sBl + (n0 + g) * GSTR + kb);
                bl[1] = *(const uint32_t*)(sBl + (n0 + g) * GSTR + kb + 8);
#pragma unroll
                for (int mt = 0; mt < 2; mt++) {
                    mma16(acc[mt][nt], ah[mt], bh);
                    mma16(acc[mt][nt], ah[mt], bl);
                    mma16(acc[mt][nt], al[mt], bh);
                }
            }
        }
    }

    float* outp;
    int noff, Nl;
    if (bn < 16)      { outp = g_xgf;  noff = 0;    Nl = 2048; }
    else if (bn < 32) { outp = g_xgb;  noff = 2048; Nl = 2048; }
    else              { outp = g_skip; noff = 4096; Nl = 1024; }

#pragma unroll
    for (int mt = 0; mt < 2; mt++) {
        int m0 = bm * 128 + wm * 32 + mt * 16 + g;
#pragma unroll
        for (int nt = 0; nt < 8; nt++) {
            int ng = bn * 128 + wn * 64 + nt * 8 + 2 * tg;
            float bias0 = g_biasc[ng], bias1 = g_biasc[ng + 1];
            int nl = ng - noff;
#pragma unroll
            for (int half = 0; half < 2; half++) {
                int m = m0 + half * 8;
                int tt = m >> 5, bb = m & 31;
                size_t base = (size_t)tt * Nl * Bz + (size_t)nl * Bz + bb;
                outp[base]      = acc[mt][nt][half * 2 + 0] + bias0;
                outp[base + Bz] = acc[mt][nt][half * 2 + 1] + bias1;
            }
        }
    }
}

// ---------------- persistent bf16 tensor-core bidirectional LSTM ----------------
// 2-chain: preact = (Whi + Wlo) x round_bf16(h). hi-only broadcast; direct-LDG frags.
#define SM_LSTM_BYTES (8 * 32 * 36 * 4)

__global__ __launch_bounds__(256, 1) void lstm_mma(
    const float* __restrict__ Whf,
    const float* __restrict__ Whb,
    const float* __restrict__ alphas)
{
    extern __shared__ float gs[];   // [8][32][36]

    const int bid = blockIdx.x;
    const int dir = (bid >= 64) ? 1 : 0;
    const int blk = dir ? bid - 64 : bid;
    const float* Wh = dir ? Whb : Whf;
    const float* xg = dir ? g_xgb : g_xgf;
    float* hs = dir ? g_hsb : g_hsf;
    int* flags = g_flag + dir * 64;

    const int tid = threadIdx.x;
    const int wid = tid >> 5, lane = tid & 31;
    const int g = lane >> 2, tg = lane & 3;
    const int cb = tid & 31;
    const int cjl = tid >> 5;
    const int cj = blk * 8 + cjl;

    // fixed fragment-slot of this thread's h element (k=cj, row=cb)
    const int kk = cj & 15, kt_own = cj >> 4;
    const int ro = cb & 15, mt_own = cb >> 4;
    const int reg_own = ((ro >= 8) ? 1 : 0) + ((kk >= 8) ? 2 : 0);
    const int ln_own = (ro & 7) * 4 + ((kk >> 1) & 3);
    const int widx = ((mt_own * 32 + kt_own) * 32 + ln_own) * 4 + reg_own;
    const int half_own = kk & 1;

    // ---- preload Wh fragments (hi/lo, packed bf16x2 along k) ----
    float whi[4][4][2], wlo[4][4][2];
#pragma unroll
    for (int nt = 0; nt < 4; nt++) {
        int n = nt * 8 + g;
        int gate = n & 3, jl = n >> 2;
        int col = gate * 512 + blk * 8 + jl;
#pragma unroll
        for (int ktl = 0; ktl < 4; ktl++) {
            int kt = wid * 4 + ktl;
#pragma unroll
            for (int r = 0; r < 2; r++) {
                int k = kt * 16 + r * 8 + 2 * tg;
                float w0 = Wh[(size_t)k * 2048 + col];
                float w1 = Wh[(size_t)(k + 1) * 2048 + col];
                __nv_bfloat16 h0, l0, h1, l1;
                bsplit(w0, h0, l0);
                bsplit(w1, h1, l1);
                whi[nt][ktl][r] = __uint_as_float(bpack(h0, h1));
                wlo[nt][ktl][r] = __uint_as_float(bpack(l0, l1));
            }
        }
    }

    float cst = 0.f, hprev = 0.f;

    for (int s = 0; s < SL; s++) {
        const int t = dir ? (SL - 1 - s) : s;

        // prefetch xg gates + alpha (independent of h)
        const size_t xb = (size_t)t * (2048 * Bz) + cb;
        float xi = xg[xb + (size_t)(0 * 512 + cj) * Bz];
        float xf = xg[xb + (size_t)(1 * 512 + cj) * Bz];
        float xv = xg[xb + (size_t)(2 * 512 + cj) * Bz];
        float xo = xg[xb + (size_t)(3 * 512 + cj) * Bz];
        float a  = alphas[cb * SL + t];

        float pi = 0.f, pf = 0.f, pg = 0.f, po = 0.f;

        if (s > 0) {
            // wait for all 64 producers of this direction (warp 0 only spins)
            if (wid == 0) {
                for (;;) {
                    int v1 = ld_acq_i(&flags[lane]);
                    int v2 = ld_acq_i(&flags[lane + 32]);
                    if (__all_sync(0xffffffffu, (v1 >= s) && (v2 >= s))) break;
                    __nanosleep(20);
                }
            }
            __syncthreads();

            // load hi A-fragments straight from L2 (frag-layout broadcast buffer)
            const size_t pbase = (size_t)(dir * 2 + ((s - 1) & 1)) * 8192;
            const uint4* fhp = (const uint4*)(g_hbh + pbase);
            uint4 fh[2][4];
#pragma unroll
            for (int mt = 0; mt < 2; mt++)
#pragma unroll
                for (int ktl = 0; ktl < 4; ktl++) {
                    int kt = wid * 4 + ktl;
                    fh[mt][ktl] = __ldcg(fhp + (mt * 32 + kt) * 32 + lane);
                }

            float acc[2][4][4];
#pragma unroll
            for (int mt = 0; mt < 2; mt++)
#pragma unroll
                for (int nt = 0; nt < 4; nt++)
#pragma unroll
                    for (int i = 0; i < 4; i++) acc[mt][nt][i] = 0.f;

#pragma unroll
            for (int ktl = 0; ktl < 4; ktl++) {
                uint32_t ah[2][4];
#pragma unroll
                for (int mt = 0; mt < 2; mt++) {
                    ah[mt][0] = fh[mt][ktl].x; ah[mt][1] = fh[mt][ktl].y;
                    ah[mt][2] = fh[mt][ktl].z; ah[mt][3] = fh[mt][ktl].w;
                }
#pragma unroll
                for (int nt = 0; nt < 4; nt++) {
                    uint32_t bh[2] = { __float_as_uint(whi[nt][ktl][0]),
                                       __float_as_uint(whi[nt][ktl][1]) };
                    uint32_t bl[2] = { __float_as_uint(wlo[nt][ktl][0]),
                                       __float_as_uint(wlo[nt][ktl][1]) };
#pragma unroll
                    for (int mt = 0; mt < 2; mt++) {
                        mma16(acc[mt][nt], ah[mt], bh);
                        mma16(acc[mt][nt], ah[mt], bl);
                    }
                }
            }

            // write partial gate sums: gs[wid][b][n]
#pragma unroll
            for (int mt = 0; mt < 2; mt++) {
#pragma unroll
                for (int nt = 0; nt < 4; nt++) {
                    int row0 = mt * 16 + g;
                    int col = nt * 8 + 2 * tg;
                    int b0i = (wid * 32 + row0) * 36 + col;
                    gs[b0i]     = acc[mt][nt][0];
                    gs[b0i + 1] = acc[mt][nt][1];
                    int b1i = (wid * 32 + row0 + 8) * 36 + col;
                    gs[b1i]     = acc[mt][nt][2];
                    gs[b1i + 1] = acc[mt][nt][3];
                }
            }
            __syncthreads();

#pragma unroll
            for (int w = 0; w < 8; w++) {
                int base = (w * 32 + cb) * 36 + cjl * 4;
                pi += gs[base + 0];
                pf += gs[base + 1];
                pg += gs[base + 2];
                po += gs[base + 3];
            }
        }

        // LSTM cell
        float gi = sigm_f(pi + xi);
        float gf = sigm_f(pf + xf);
        float gG = tanh_f(pg + xv);
        float go = sigm_f(po + xo);

        float cn = gf * cst + gi * gG;
        float hn = go * tanh_f(cn);

        cst = a * cn + (1.f - a) * cst;
        float h2 = a * hn + (1.f - a) * hprev;
        hprev = h2;

        hs[(size_t)t * (HD * Bz) + cj * 32 + cb] = h2;

        // publish h (hi plane only) in frag layout
        {
            __nv_bfloat16 hi = __float2bfloat16_rn(h2);
            size_t pb = (size_t)(dir * 2 + (s & 1)) * 8192;
            ((__nv_bfloat16*)(g_hbh + pb))[widx * 2 + half_own] = hi;
        }

        __syncthreads();
        if (tid == 0) { __threadfence(); st_rel_i(&flags[blk], s + 1); }
    }
}

// ---------------- pooling ----------------
__global__ void pool_kernel(const float* __restrict__ alphas, float* __restrict__ out)
{
    const int tid = blockIdx.x * blockDim.x + threadIdx.x;
    const int b = tid & 31;
    const int g = tid >> 5;
    if (g >= 1024) return;

    const float* top = (g < HD) ? (g_hsf + (size_t)g * 32 + b)
                                : (g_hsb + (size_t)(g - HD) * 32 + b);
    const float* sk = g_skip + (size_t)g * 32 + b;

    float sum = 0.f, asum = 0.f, mx = -INFINITY;
    for (int t = 0; t < SL; t++) {
        float a = alphas[b * SL + t];
        float r = (top[(size_t)t * (HD * Bz)] + sk[(size_t)t * (1024 * Bz)]) * a;
        sum += r;
        asum += a;
        if (a > 0.f) mx = fmaxf(mx, r);
    }
    float mean = sum / (asum + 1e-6f);
    if (isinf(mx)) mx = 0.f;
    out[b * 2048 + g] = mean;
    out[b * 2048 + 1024 + g] = mx;
}

// ---------------- launch ----------------
extern "C" void kernel_launch(void* const* d_in, const int* in_sizes, int n_in,
                              void* d_out, int out_size)
{
    const float* values = (const float*)d_in[0];
    const float* alphas = (const float*)d_in[1];
    const float* Wx_f = (const float*)d_in[2];
    const float* Wh_f = (const float*)d_in[3];
    const float* b_f  = (const float*)d_in[4];
    const float* Wx_b = (const float*)d_in[5];
    const float* Wh_b = (const float*)d_in[6];
    const float* b_b  = (const float*)d_in[7];
    const float* Ws   = (const float*)d_in[8];
    const float* bs   = (const float*)d_in[9];
    float* out = (float*)d_out;

    cudaFuncSetAttribute(gemm_mma, cudaFuncAttributeMaxDynamicSharedMemorySize, 57344);
    cudaFuncSetAttribute(lstm_mma, cudaFuncAttributeMaxDynamicSharedMemorySize, SM_LSTM_BYTES);

    init_misc<<<20, 256>>>(b_f, b_b, bs);
    split_A<<<Bz * SL, 256>>>(values);
    split_W<<<dim3(VD / 32, NT / 32), 256>>>(Wx_f, Wx_b, Ws);
    gemm_mma<<<dim3(NT / 128, (Bz * SL) / 128), 256, 57344>>>();
    lstm_mma<<<NBLK, 256, SM_LSTM_BYTES>>>(Wh_f, Wh_b, alphas);
    pool_kernel<<<(Bz * 1024) / 256, 256>>>(alphas, out);
}